// round 15
// baseline (speedup 1.0000x reference)
#include <cuda_runtime.h>
#include <cuda_bf16.h>
#include <math.h>
#include <float.h>
#include <stdint.h>

// ---------------- problem constants ----------------
#define NN        8192
#define EE        65536
#define M1        16
#define M2        16
#define HS        64        // M2*D
#define NH        4
#define EDGE_DIM  32
#define EHID      64
#define NI        96        // output dim (GEMM N)
#define NJ        32        // M1*K
#define NSLAB     33        // 64-k slabs (2080 real + 32 zero/bias rows)
#define EB        128       // edges per CTA (GEMM M)
#define NT        256       // threads per CTA (8 warps)

// ---------------- device scratch ----------------
// W pre-packed in mma.m16n8k16 B-fragment layout:
// g_Wf[((s*4+ks)*12+nf)*32+lane] = {hi_reg0, hi_reg1, lo_reg0, lo_reg1}
__device__ __align__(16) uint4 g_Wf[NSLAB * 4 * 12 * 32];
__device__ float g_h[66 * EE];          // h[c][e]; rows 64=1, 65=0 (bias/pad)
__device__ float g_scores[EE * NH];
__device__ __align__(16) float g_v[EE * HS];
__device__ float g_nmax[NN * NH];
__device__ float g_nsum[NN * NH];
__device__ float g_agg[NN * HS];

// ---------------- smem layout (bytes) ----------------
// G buf b (b=0,1): hi at b*32768, lo at b*32768+16384  (128 rows x 128B, XOR-swizzled)
// W buf b: 65536 + b*24576   (4ks x 12nf x 32lane x 16B)
// t2_s (96 x 128 f32 = 48KB) overlays G buffers after the loop.
#define SO_GBUF(b)  ((b) * 32768)
#define GLO_OFF     16384
#define SO_W(b)     (65536 + (b) * 24576)
#define SMEM_BYTES  114688

// ---------------- ptx helpers ----------------
__device__ __forceinline__ void cp_async16(uint32_t saddr, const void* gsrc) {
    asm volatile("cp.async.cg.shared.global [%0], [%1], 16;" :: "r"(saddr), "l"(gsrc));
}
#define CP_COMMIT() asm volatile("cp.async.commit_group;" ::: "memory")
#define CP_WAIT0()  asm volatile("cp.async.wait_group 0;" ::: "memory")

__device__ __forceinline__ void ldsm4(uint32_t* r, uint32_t saddr) {
    asm volatile("ldmatrix.sync.aligned.m8n8.x4.shared.b16 {%0,%1,%2,%3}, [%4];"
        : "=r"(r[0]), "=r"(r[1]), "=r"(r[2]), "=r"(r[3]) : "r"(saddr));
}
__device__ __forceinline__ void hmma(float* c, const uint32_t* a, uint32_t b0, uint32_t b1) {
    asm volatile(
        "mma.sync.aligned.m16n8k16.row.col.f32.bf16.bf16.f32 "
        "{%0,%1,%2,%3}, {%4,%5,%6,%7}, {%8,%9}, {%0,%1,%2,%3};"
        : "+f"(c[0]), "+f"(c[1]), "+f"(c[2]), "+f"(c[3])
        : "r"(a[0]), "r"(a[1]), "r"(a[2]), "r"(a[3]), "r"(b0), "r"(b1));
}
// pack two f32 -> bf16x2, v0 in lower 16 bits
__device__ __forceinline__ uint32_t pack_bf16x2(float v0, float v1) {
    uint32_t r;
    asm("cvt.rn.bf16x2.f32 %0, %1, %2;" : "=r"(r) : "f"(v1), "f"(v0));
    return r;
}

__device__ __forceinline__ void atomicMaxF(float* addr, float val) {
    int old = __float_as_int(*addr);
    while (__int_as_float(old) < val) {
        int assumed = old;
        old = atomicCAS(reinterpret_cast<int*>(addr), assumed, __float_as_int(val));
        if (old == assumed) break;
    }
}

// ---------------- kernel 0a: pre-split W into B-fragment layout ----------------
__device__ __forceinline__ float fetchW(const float* w2, const float* b2, int k, int n) {
    if (k < 2048) return w2[(k >> 5) * (NI * NJ) + n * NJ + (k & 31)];
    if (k < 2080) return b2[n * NJ + (k - 2048)];
    return 0.f;
}
__global__ void k_prepB(const float* __restrict__ w2, const float* __restrict__ b2) {
    int idx = blockIdx.x * blockDim.x + threadIdx.x;
    if (idx >= NSLAB * 4 * 12 * 32) return;
    int lane = idx & 31;
    int t    = idx >> 5;
    int nf   = t % 12;
    int t2   = t / 12;
    int ks   = t2 & 3;
    int s    = t2 >> 2;
    int ksg  = s * 4 + ks;
    int n    = nf * 8 + lane / 4;
    int kb   = ksg * 16 + (lane & 3) * 2;

    float w[4];
    w[0] = fetchW(w2, b2, kb,     n);
    w[1] = fetchW(w2, b2, kb + 1, n);
    w[2] = fetchW(w2, b2, kb + 8, n);
    w[3] = fetchW(w2, b2, kb + 9, n);

    float hi[4], lo[4];
    #pragma unroll
    for (int q = 0; q < 4; ++q) {
        hi[q] = __bfloat162float(__float2bfloat16(w[q]));
        lo[q] = w[q] - hi[q];
    }
    g_Wf[idx] = make_uint4(pack_bf16x2(hi[0], hi[1]), pack_bf16x2(hi[2], hi[3]),
                           pack_bf16x2(lo[0], lo[1]), pack_bf16x2(lo[2], lo[3]));
}

// ---------------- kernel 0b: edge-MLP hidden h[c][e] ----------------
__global__ void __launch_bounds__(256) k_hid(
    const float* __restrict__ ef, const float* __restrict__ w1,
    const float* __restrict__ bias1)
{
    __shared__ float w1_s[EDGE_DIM * EHID];
    __shared__ float b1_s[EHID];
    int tid = threadIdx.x;
    for (int i = tid; i < EDGE_DIM * EHID; i += 256) w1_s[i] = w1[i];
    if (tid < EHID) b1_s[tid] = bias1[tid];
    __syncthreads();

    int e = blockIdx.x * 256 + tid;
    float efr[EDGE_DIM];
    #pragma unroll
    for (int x = 0; x < EDGE_DIM; ++x) efr[x] = ef[e * EDGE_DIM + x];
    #pragma unroll 4
    for (int c = 0; c < EHID; ++c) {
        float s = b1_s[c];
        #pragma unroll
        for (int x = 0; x < EDGE_DIM; ++x) s = fmaf(efr[x], w1_s[x * EHID + c], s);
        g_h[c * EE + e] = fmaxf(s, 0.f);
    }
    g_h[64 * EE + e] = 1.f;   // bias rows (first 32 k of slab 32)
    g_h[65 * EE + e] = 0.f;   // zero pad  (last 32 k of slab 32)
}

// ---------------- kernel 0c: reset reductions ----------------
__global__ void k_init() {
    int idx = blockIdx.x * blockDim.x + threadIdx.x;
    if (idx < NN * HS) g_agg[idx] = 0.f;
    if (idx < NN * NH) { g_nmax[idx] = -FLT_MAX; g_nsum[idx] = 0.f; }
}

// ---------------- kernel 1: pipelined bf16x3 mma.sync, 8 warps ----------------
__global__ void __launch_bounds__(NT, 2) k_edge(
    const float* __restrict__ f,
    const float* __restrict__ b1, const float* __restrict__ b2,
    const int*   __restrict__ src_idx, const int* __restrict__ dst_idx)
{
    extern __shared__ __align__(16) char smem[];
    const uint32_t sb = (uint32_t)__cvta_generic_to_shared(smem);
    float* t2_s = reinterpret_cast<float*>(smem);

    const int tid  = threadIdx.x;
    const int wid  = tid >> 5;
    const int lane = tid & 31;
    const int el   = tid & 127;      // edge lane within CTA tile
    const int sub  = tid >> 7;       // j-half: sub*16 .. sub*16+15
    const int e    = blockIdx.x * EB + el;

    // --- t[j] for this thread's j-half in registers: j = sub*16 + jj ---
    float t_r[16];
    {
        const int s = src_idx[e];
        float b1r[8];
        #pragma unroll
        for (int z = 0; z < 8; ++z) b1r[z] = b1[e * 8 + z];   // [d][k]
        const float4* frow = reinterpret_cast<const float4*>(f) + s * M1;
        #pragma unroll
        for (int mm = 0; mm < 8; ++mm) {
            float4 fv = frow[sub * 8 + mm];      // j = 2m+k, m = sub*8+mm
            t_r[2*mm+0] = fv.x*b1r[0] + fv.y*b1r[2] + fv.z*b1r[4] + fv.w*b1r[6];
            t_r[2*mm+1] = fv.x*b1r[1] + fv.y*b1r[3] + fv.z*b1r[5] + fv.w*b1r[7];
        }
    }

    // build helper: this thread writes 4 of the 8 chunks of edge el's G row:
    // chunks c = (cl<<2) | g with g in {sub*2, sub*2+1}; chunk c covers j = (c&3)*8..+7
    const int rowoff = el * 128;
    const int rsw    = el & 7;

    auto build_g = [&](int buf, float hv0, float hv1) {
        char* gh = smem + SO_GBUF(buf) + rowoff;
        char* gl = gh + GLO_OFF;
        #pragma unroll
        for (int cl = 0; cl < 2; ++cl) {
            float hv = cl ? hv1 : hv0;
            #pragma unroll
            for (int gg = 0; gg < 2; ++gg) {
                int g = sub * 2 + gg;            // global j-chunk 0..3
                float v[8];
                #pragma unroll
                for (int q = 0; q < 8; ++q) v[q] = hv * t_r[gg * 8 + q];
                uint32_t H[4], L[4];
                #pragma unroll
                for (int p = 0; p < 4; ++p) {
                    H[p] = pack_bf16x2(v[2*p], v[2*p+1]);
                    float f0 = __uint_as_float(H[p] << 16);
                    float f1 = __uint_as_float(H[p] & 0xffff0000u);
                    L[p] = pack_bf16x2(v[2*p] - f0, v[2*p+1] - f1);
                }
                int sw = (((cl << 2) | g) ^ rsw) << 4;
                *reinterpret_cast<uint4*>(gh + sw) = make_uint4(H[0], H[1], H[2], H[3]);
                *reinterpret_cast<uint4*>(gl + sw) = make_uint4(L[0], L[1], L[2], L[3]);
            }
        }
    };

    // prologue: h(0),h(1); build G(0); prefetch W(0)
    float h0a = g_h[0 * EE + e], h0b = g_h[1 * EE + e];
    float hna = g_h[2 * EE + e], hnb = g_h[3 * EE + e];

    build_g(0, h0a, h0b);
    {   // prefetch W(0): 1536 uint4 / 256 threads = 6 each
        const uint4* wsrc = g_Wf;
        #pragma unroll
        for (int q = 0; q < 6; ++q)
            cp_async16(sb + SO_W(0) + (q * NT + tid) * 16, wsrc + q * NT + tid);
        CP_COMMIT();
    }

    // warp tiling: 8 warps = 4 m-blocks (32 rows, 2 mf) x 2 n-halves (6 nf)
    const int nbase = (wid & 1) * 6;
    const int ebq   = (wid >> 1) * 32;

    float acc[2][6][4];
    #pragma unroll
    for (int mf = 0; mf < 2; ++mf)
        #pragma unroll
        for (int nf = 0; nf < 6; ++nf)
            #pragma unroll
            for (int q = 0; q < 4; ++q) acc[mf][nf][q] = 0.f;

    const int rl    = lane & 15;
    const int chbit = lane >> 4;

    for (int s = 0; s < NSLAB; ++s) {
        CP_WAIT0();          // W(s) landed
        __syncthreads();     // G(s) built & visible; MMA(s-1) reads complete

        // prefetch W(s+1) into alt buf
        if (s + 1 < NSLAB) {
            const uint4* wsrc = g_Wf + (s + 1) * 1536;
            #pragma unroll
            for (int q = 0; q < 6; ++q)
                cp_async16(sb + SO_W((s + 1) & 1) + (q * NT + tid) * 16,
                           wsrc + q * NT + tid);
            CP_COMMIT();
        }

        // build G(s+1) into alt buf; stage h(s+2)
        if (s + 1 < NSLAB) {
            float ha = hna, hb = hnb;
            if (s + 2 < NSLAB) {
                hna = g_h[(2 * s + 4) * EE + e];
                hnb = g_h[(2 * s + 5) * EE + e];
            }
            build_g((s + 1) & 1, ha, hb);
        }

        // MMA(s): reads G buf s&1, W buf s&1
        const uint32_t gbase = sb + SO_GBUF(s & 1);
        const char*    wb    = smem + SO_W(s & 1);
        #pragma unroll
        for (int ks = 0; ks < 4; ++ks) {
            uint32_t Ah[2][4], Al[2][4];
            #pragma unroll
            for (int mf = 0; mf < 2; ++mf) {
                int r  = ebq + mf * 16 + rl;
                int sw = (((ks << 1) | chbit) ^ (r & 7)) << 4;
                uint32_t ra = gbase + r * 128 + sw;
                ldsm4(Ah[mf], ra);
                ldsm4(Al[mf], ra + GLO_OFF);
            }
            #pragma unroll
            for (int nf = 0; nf < 6; ++nf) {
                uint4 B = *reinterpret_cast<const uint4*>(
                    wb + ((ks * 12 + nbase + nf) * 32 + lane) * 16);
                #pragma unroll
                for (int mf = 0; mf < 2; ++mf) {
                    hmma(acc[mf][nf], Ah[mf], B.x, B.y);   // hi*hi
                    hmma(acc[mf][nf], Ah[mf], B.z, B.w);   // hi*lo
                    hmma(acc[mf][nf], Al[mf], B.x, B.y);   // lo*hi
                }
            }
        }
    }

    __syncthreads();   // all LDSM of final slab done; G bufs reusable as t2_s
    #pragma unroll
    for (int mf = 0; mf < 2; ++mf) {
        int e0 = ebq + mf * 16 + lane / 4;
        #pragma unroll
        for (int nf = 0; nf < 6; ++nf) {
            int i0 = (nbase + nf) * 8 + (lane & 3) * 2;
            t2_s[(i0    ) * EB + e0    ] = acc[mf][nf][0];
            t2_s[(i0 + 1) * EB + e0    ] = acc[mf][nf][1];
            t2_s[(i0    ) * EB + e0 + 8] = acc[mf][nf][2];
            t2_s[(i0 + 1) * EB + e0 + 8] = acc[mf][nf][3];
        }
    }
    __syncthreads();

    // --- epilogue: conv = t2 . basis2 ; scores ; v  (o-range split by sub) ---
    {
        float b2r[8];
        #pragma unroll
        for (int z = 0; z < 8; ++z) b2r[z] = b2[e * 8 + z];   // [p][d]

        float sc0 = 0.f, sc1 = 0.f;        // heads sub*2, sub*2+1
        #pragma unroll
        for (int o8 = 0; o8 < 8; ++o8) {
            int o = sub * 8 + o8;
            float a0 = t2_s[(2 * o) * EB + el],      a1 = t2_s[(2 * o + 1) * EB + el];
            float q0 = t2_s[(2 * o + 32) * EB + el], q1 = t2_s[(2 * o + 33) * EB + el];
            float dot = 0.f;
            #pragma unroll
            for (int d = 0; d < 4; ++d) {
                float kk = a0 * b2r[d] + a1 * b2r[4 + d];
                float qq = q0 * b2r[d] + q1 * b2r[4 + d];
                dot = fmaf(kk, qq, dot);
            }
            if (o8 < 4) sc0 += dot; else sc1 += dot;
        }
        #pragma unroll
        for (int o8 = 0; o8 < 8; ++o8) {
            int o = sub * 8 + o8;
            float a0 = t2_s[(2 * o + 64) * EB + el], a1 = t2_s[(2 * o + 65) * EB + el];
            float4 vv;
            vv.x = a0 * b2r[0] + a1 * b2r[4];
            vv.y = a0 * b2r[1] + a1 * b2r[5];
            vv.z = a0 * b2r[2] + a1 * b2r[6];
            vv.w = a0 * b2r[3] + a1 * b2r[7];
            reinterpret_cast<float4*>(g_v)[e * 16 + o] = vv;
        }
        const int dn = dst_idx[e];
        #pragma unroll
        for (int hq = 0; hq < 2; ++hq) {
            int hh = sub * 2 + hq;
            float s = (hq == 0 ? sc0 : sc1) * 0.125f;   // TEMP = HS^-0.5
            s = (s > 0.f) ? s : 0.2f * s;               // leaky_relu(., 0.2)
            g_scores[e * NH + hh] = s;
            atomicMaxF(&g_nmax[dn * NH + hh], s);
        }
    }
}

// ---------------- kernel 2: softmax denominator ----------------
__global__ void k_sum(const int* __restrict__ dst_idx) {
    int idx = blockIdx.x * blockDim.x + threadIdx.x;
    if (idx >= EE * NH) return;
    int e = idx >> 2, hh = idx & 3;
    int dn = dst_idx[e];
    float ex = expf(g_scores[idx] - g_nmax[dn * NH + hh]);
    atomicAdd(&g_nsum[dn * NH + hh], ex);
}

// ---------------- kernel 3: weighted aggregation (copy_e_sum) ----------------
__global__ void k_agg(const int* __restrict__ dst_idx) {
    int idx = blockIdx.x * blockDim.x + threadIdx.x;
    if (idx >= EE * HS) return;
    int e = idx >> 6, x = idx & 63, hh = x >> 4;
    int dn = dst_idx[e];
    float w = expf(g_scores[e * NH + hh] - g_nmax[dn * NH + hh]) / g_nsum[dn * NH + hh];
    atomicAdd(&g_agg[dn * HS + x], w * g_v[idx]);
}

// ---------------- kernel 4: per-irrep equivariant projection ----------------
__global__ void k_proj(const float* __restrict__ pw, const float* __restrict__ pb,
                       float* __restrict__ out) {
    int idx = blockIdx.x * blockDim.x + threadIdx.x;
    if (idx >= NN * HS) return;
    int n  = idx >> 6;
    int m2 = (idx >> 2) & 15;
    int d  = idx & 3;
    int blk = (d == 0) ? 0 : 1;                // IRREP_IDX = [0,1,1,1]
    const float* pwr = pw + (blk * M2 + m2) * M2;
    float s = (d == 0) ? pb[m2] : 0.f;
    #pragma unroll
    for (int m = 0; m < M2; ++m) s = fmaf(pwr[m], g_agg[n * HS + m * 4 + d], s);
    out[idx] = s;
}

// ---------------- launch ----------------
extern "C" void kernel_launch(void* const* d_in, const int* in_sizes, int n_in,
                              void* d_out, int out_size) {
    const float* ef    = (const float*)d_in[0];   // edge_feats (E,32)
    const float* f     = (const float*)d_in[1];   // f (N,16,4)
    const float* b1    = (const float*)d_in[2];   // basis1 (E,4,2)
    const float* b2    = (const float*)d_in[3];   // basis2 (E,2,4)
    const int*   src   = (const int*)  d_in[4];   // src_idx (E)
    const int*   dst   = (const int*)  d_in[5];   // dst_idx (E)
    const float* w1    = (const float*)d_in[6];   // rw_w1 (32,64)
    const float* bias1 = (const float*)d_in[7];   // rw_bias1 (64)
    const float* w2    = (const float*)d_in[8];   // rw_w2 (64,3072)
    const float* bias2 = (const float*)d_in[9];   // rw_bias2 (3072)
    const float* pw    = (const float*)d_in[10];  // proj_w (32,16)
    const float* pb    = (const float*)d_in[11];  // proj_b (16,1)
    float* out = (float*)d_out;

    (void)in_sizes; (void)n_in; (void)out_size;

    cudaFuncSetAttribute(k_edge, cudaFuncAttributeMaxDynamicSharedMemorySize, SMEM_BYTES);

    k_prepB<<<(NSLAB * 4 * 12 * 32 + 255) / 256, 256>>>(w2, bias2);
    k_hid<<<EE / 256, 256>>>(ef, w1, bias1);
    k_init<<<(NN * HS + 255) / 256, 256>>>();
    k_edge<<<EE / EB, NT, SMEM_BYTES>>>(f, b1, b2, src, dst);
    k_sum<<<(EE * NH + 255) / 256, 256>>>(dst);
    k_agg<<<(EE * HS + 255) / 256, 256>>>(dst);
    k_proj<<<(NN * HS + 255) / 256, 256>>>(pw, pb, out);
}

// round 16
// speedup vs baseline: 1.0411x; 1.0411x over previous
#include <cuda_runtime.h>
#include <cuda_bf16.h>
#include <math.h>
#include <float.h>
#include <stdint.h>

// ---------------- problem constants ----------------
#define NN        8192
#define EE        65536
#define M1        16
#define M2        16
#define HS        64        // M2*D
#define NH        4
#define EDGE_DIM  32
#define EHID      64
#define NI        96        // output dim (GEMM N)
#define NJ        32        // M1*K
#define NSLAB     33        // 64-k slabs (2080 real + 32 zero/bias rows)
#define EB        128       // edges per CTA (GEMM M)
#define NT        256       // threads per CTA (8 warps)

// ---------------- device scratch ----------------
// W pre-packed in mma.m16n8k16 B-fragment layout:
// g_Wf[((s*4+ks)*12+nf)*32+lane] = {hi_reg0, hi_reg1, lo_reg0, lo_reg1}
__device__ __align__(16) uint4 g_Wf[NSLAB * 4 * 12 * 32];
__device__ float g_h[66 * EE];          // h[c][e]; rows 64=1, 65=0 (bias/pad)
__device__ float g_scores[EE * NH];
__device__ __align__(16) float g_v[EE * HS];
__device__ float g_nmax[NN * NH];
__device__ float g_nsum[NN * NH];
__device__ float g_agg[NN * HS];

// ---------------- smem layout (bytes) ----------------
// G buf b (b=0,1): hi at b*32768, lo at b*32768+16384  (128 rows x 128B, XOR-swizzled)
// W buf b: 65536 + b*24576   (4ks x 12nf x 32lane x 16B)
// t2_s (96 x 128 f32 = 48KB) overlays G buffers after the loop.
#define SO_GBUF(b)  ((b) * 32768)
#define GLO_OFF     16384
#define SO_W(b)     (65536 + (b) * 24576)
#define SMEM_BYTES  114688

// ---------------- ptx helpers ----------------
__device__ __forceinline__ void cp_async16(uint32_t saddr, const void* gsrc) {
    asm volatile("cp.async.cg.shared.global [%0], [%1], 16;" :: "r"(saddr), "l"(gsrc));
}
#define CP_COMMIT() asm volatile("cp.async.commit_group;" ::: "memory")
#define CP_WAIT0()  asm volatile("cp.async.wait_group 0;" ::: "memory")

__device__ __forceinline__ void ldsm4(uint32_t* r, uint32_t saddr) {
    asm volatile("ldmatrix.sync.aligned.m8n8.x4.shared.b16 {%0,%1,%2,%3}, [%4];"
        : "=r"(r[0]), "=r"(r[1]), "=r"(r[2]), "=r"(r[3]) : "r"(saddr));
}
__device__ __forceinline__ void hmma(float* c, const uint32_t* a, uint32_t b0, uint32_t b1) {
    asm volatile(
        "mma.sync.aligned.m16n8k16.row.col.f32.bf16.bf16.f32 "
        "{%0,%1,%2,%3}, {%4,%5,%6,%7}, {%8,%9}, {%0,%1,%2,%3};"
        : "+f"(c[0]), "+f"(c[1]), "+f"(c[2]), "+f"(c[3])
        : "r"(a[0]), "r"(a[1]), "r"(a[2]), "r"(a[3]), "r"(b0), "r"(b1));
}
// pack two f32 -> bf16x2, v0 in lower 16 bits
__device__ __forceinline__ uint32_t pack_bf16x2(float v0, float v1) {
    uint32_t r;
    asm("cvt.rn.bf16x2.f32 %0, %1, %2;" : "=r"(r) : "f"(v1), "f"(v0));
    return r;
}

__device__ __forceinline__ void atomicMaxF(float* addr, float val) {
    int old = __float_as_int(*addr);
    while (__int_as_float(old) < val) {
        int assumed = old;
        old = atomicCAS(reinterpret_cast<int*>(addr), assumed, __float_as_int(val));
        if (old == assumed) break;
    }
}

// ---------------- kernel 0a: pre-split W into B-fragment layout ----------------
__device__ __forceinline__ float fetchW(const float* w2, const float* b2, int k, int n) {
    if (k < 2048) return w2[(k >> 5) * (NI * NJ) + n * NJ + (k & 31)];
    if (k < 2080) return b2[n * NJ + (k - 2048)];
    return 0.f;
}
__global__ void k_prepB(const float* __restrict__ w2, const float* __restrict__ b2) {
    int idx = blockIdx.x * blockDim.x + threadIdx.x;
    if (idx >= NSLAB * 4 * 12 * 32) return;
    int lane = idx & 31;
    int t    = idx >> 5;
    int nf   = t % 12;
    int t2   = t / 12;
    int ks   = t2 & 3;
    int s    = t2 >> 2;
    int ksg  = s * 4 + ks;
    int n    = nf * 8 + lane / 4;
    int kb   = ksg * 16 + (lane & 3) * 2;

    float w[4];
    w[0] = fetchW(w2, b2, kb,     n);
    w[1] = fetchW(w2, b2, kb + 1, n);
    w[2] = fetchW(w2, b2, kb + 8, n);
    w[3] = fetchW(w2, b2, kb + 9, n);

    float hi[4], lo[4];
    #pragma unroll
    for (int q = 0; q < 4; ++q) {
        hi[q] = __bfloat162float(__float2bfloat16(w[q]));
        lo[q] = w[q] - hi[q];
    }
    g_Wf[idx] = make_uint4(pack_bf16x2(hi[0], hi[1]), pack_bf16x2(hi[2], hi[3]),
                           pack_bf16x2(lo[0], lo[1]), pack_bf16x2(lo[2], lo[3]));
}

// ---------------- kernel 0b: edge-MLP hidden h[c][e] ----------------
__global__ void __launch_bounds__(256) k_hid(
    const float* __restrict__ ef, const float* __restrict__ w1,
    const float* __restrict__ bias1)
{
    __shared__ float w1_s[EDGE_DIM * EHID];
    __shared__ float b1_s[EHID];
    int tid = threadIdx.x;
    for (int i = tid; i < EDGE_DIM * EHID; i += 256) w1_s[i] = w1[i];
    if (tid < EHID) b1_s[tid] = bias1[tid];
    __syncthreads();

    int e = blockIdx.x * 256 + tid;
    float efr[EDGE_DIM];
    #pragma unroll
    for (int x = 0; x < EDGE_DIM; ++x) efr[x] = ef[e * EDGE_DIM + x];
    #pragma unroll 4
    for (int c = 0; c < EHID; ++c) {
        float s = b1_s[c];
        #pragma unroll
        for (int x = 0; x < EDGE_DIM; ++x) s = fmaf(efr[x], w1_s[x * EHID + c], s);
        g_h[c * EE + e] = fmaxf(s, 0.f);
    }
    g_h[64 * EE + e] = 1.f;   // bias rows (first 32 k of slab 32)
    g_h[65 * EE + e] = 0.f;   // zero pad  (last 32 k of slab 32)
}

// ---------------- kernel 0c: reset reductions ----------------
__global__ void k_init() {
    int idx = blockIdx.x * blockDim.x + threadIdx.x;
    if (idx < NN * HS) g_agg[idx] = 0.f;
    if (idx < NN * NH) { g_nmax[idx] = -FLT_MAX; g_nsum[idx] = 0.f; }
}

// ---------------- kernel 1: pipelined bf16x3 mma.sync, 8 warps ----------------
// Loop body: wait W(s) -> barrier -> prefetch W(s+1) -> MMA(s) -> build G(s+1).
// MMA inner: term-major with all 6 B fragments preloaded per ks (12 indep acc chains).
__global__ void __launch_bounds__(NT, 2) k_edge(
    const float* __restrict__ f,
    const float* __restrict__ b1, const float* __restrict__ b2,
    const int*   __restrict__ src_idx, const int* __restrict__ dst_idx)
{
    extern __shared__ __align__(16) char smem[];
    const uint32_t sb = (uint32_t)__cvta_generic_to_shared(smem);
    float* t2_s = reinterpret_cast<float*>(smem);

    const int tid  = threadIdx.x;
    const int wid  = tid >> 5;
    const int lane = tid & 31;
    const int el   = tid & 127;      // edge lane within CTA tile
    const int sub  = tid >> 7;       // j-half: sub*16 .. sub*16+15
    const int e    = blockIdx.x * EB + el;

    // --- t[j] for this thread's j-half in registers: j = sub*16 + jj ---
    float t_r[16];
    {
        const int s = src_idx[e];
        float b1r[8];
        #pragma unroll
        for (int z = 0; z < 8; ++z) b1r[z] = b1[e * 8 + z];   // [d][k]
        const float4* frow = reinterpret_cast<const float4*>(f) + s * M1;
        #pragma unroll
        for (int mm = 0; mm < 8; ++mm) {
            float4 fv = frow[sub * 8 + mm];      // j = 2m+k, m = sub*8+mm
            t_r[2*mm+0] = fv.x*b1r[0] + fv.y*b1r[2] + fv.z*b1r[4] + fv.w*b1r[6];
            t_r[2*mm+1] = fv.x*b1r[1] + fv.y*b1r[3] + fv.z*b1r[5] + fv.w*b1r[7];
        }
    }

    // build helper: this thread writes 4 of the 8 chunks of edge el's G row:
    // chunks c = (cl<<2) | g with g in {sub*2, sub*2+1}; chunk c covers j = (c&3)*8..+7
    const int rowoff = el * 128;
    const int rsw    = el & 7;

    auto build_g = [&](int buf, float hv0, float hv1) {
        char* gh = smem + SO_GBUF(buf) + rowoff;
        char* gl = gh + GLO_OFF;
        #pragma unroll
        for (int cl = 0; cl < 2; ++cl) {
            float hv = cl ? hv1 : hv0;
            #pragma unroll
            for (int gg = 0; gg < 2; ++gg) {
                int g = sub * 2 + gg;            // global j-chunk 0..3
                float v[8];
                #pragma unroll
                for (int q = 0; q < 8; ++q) v[q] = hv * t_r[gg * 8 + q];
                uint32_t H[4], L[4];
                #pragma unroll
                for (int p = 0; p < 4; ++p) {
                    H[p] = pack_bf16x2(v[2*p], v[2*p+1]);
                    float f0 = __uint_as_float(H[p] << 16);
                    float f1 = __uint_as_float(H[p] & 0xffff0000u);
                    L[p] = pack_bf16x2(v[2*p] - f0, v[2*p+1] - f1);
                }
                int sw = (((cl << 2) | g) ^ rsw) << 4;
                *reinterpret_cast<uint4*>(gh + sw) = make_uint4(H[0], H[1], H[2], H[3]);
                *reinterpret_cast<uint4*>(gl + sw) = make_uint4(L[0], L[1], L[2], L[3]);
            }
        }
    };

    // prologue: h(0),h(1); build G(0); prefetch W(0)
    float h0a = g_h[0 * EE + e], h0b = g_h[1 * EE + e];
    float hna = g_h[2 * EE + e], hnb = g_h[3 * EE + e];

    build_g(0, h0a, h0b);
    {   // prefetch W(0): 1536 uint4 / 256 threads = 6 each
        const uint4* wsrc = g_Wf;
        #pragma unroll
        for (int q = 0; q < 6; ++q)
            cp_async16(sb + SO_W(0) + (q * NT + tid) * 16, wsrc + q * NT + tid);
        CP_COMMIT();
    }

    // warp tiling: 8 warps = 4 m-blocks (32 rows, 2 mf) x 2 n-halves (6 nf)
    const int nbase = (wid & 1) * 6;
    const int ebq   = (wid >> 1) * 32;

    float acc[2][6][4];
    #pragma unroll
    for (int mf = 0; mf < 2; ++mf)
        #pragma unroll
        for (int nf = 0; nf < 6; ++nf)
            #pragma unroll
            for (int q = 0; q < 4; ++q) acc[mf][nf][q] = 0.f;

    const int rl    = lane & 15;
    const int chbit = lane >> 4;

    for (int s = 0; s < NSLAB; ++s) {
        CP_WAIT0();          // W(s) landed
        __syncthreads();     // G(s) built & visible; prior MMA smem reads complete

        // prefetch W(s+1) into alt buf
        if (s + 1 < NSLAB) {
            const uint4* wsrc = g_Wf + (s + 1) * 1536;
            #pragma unroll
            for (int q = 0; q < 6; ++q)
                cp_async16(sb + SO_W((s + 1) & 1) + (q * NT + tid) * 16,
                           wsrc + q * NT + tid);
            CP_COMMIT();
        }

        // MMA(s) FIRST: fill the tensor queue, then build overlaps the drain.
        const uint32_t gbase = sb + SO_GBUF(s & 1);
        const char*    wb    = smem + SO_W(s & 1);
        #pragma unroll
        for (int ks = 0; ks < 4; ++ks) {
            uint32_t Ah[2][4], Al[2][4];
            #pragma unroll
            for (int mf = 0; mf < 2; ++mf) {
                int r  = ebq + mf * 16 + rl;
                int sw = (((ks << 1) | chbit) ^ (r & 7)) << 4;
                uint32_t ra = gbase + r * 128 + sw;
                ldsm4(Ah[mf], ra);
                ldsm4(Al[mf], ra + GLO_OFF);
            }
            // preload all 6 B fragments for this ks
            uint4 Bv[6];
            #pragma unroll
            for (int nf = 0; nf < 6; ++nf)
                Bv[nf] = *reinterpret_cast<const uint4*>(
                    wb + ((ks * 12 + nbase + nf) * 32 + lane) * 16);
            // term-major emission: 12 independent acc chains per pass
            #pragma unroll
            for (int nf = 0; nf < 6; ++nf)
                #pragma unroll
                for (int mf = 0; mf < 2; ++mf)
                    hmma(acc[mf][nf], Ah[mf], Bv[nf].x, Bv[nf].y);   // hi*hi
            #pragma unroll
            for (int nf = 0; nf < 6; ++nf)
                #pragma unroll
                for (int mf = 0; mf < 2; ++mf)
                    hmma(acc[mf][nf], Ah[mf], Bv[nf].z, Bv[nf].w);   // hi*lo
            #pragma unroll
            for (int nf = 0; nf < 6; ++nf)
                #pragma unroll
                for (int mf = 0; mf < 2; ++mf)
                    hmma(acc[mf][nf], Al[mf], Bv[nf].x, Bv[nf].y);   // lo*hi
        }

        // build G(s+1) into alt buf; stage h(s+2)
        if (s + 1 < NSLAB) {
            float ha = hna, hb = hnb;
            if (s + 2 < NSLAB) {
                hna = g_h[(2 * s + 4) * EE + e];
                hnb = g_h[(2 * s + 5) * EE + e];
            }
            build_g((s + 1) & 1, ha, hb);
        }
    }

    __syncthreads();   // all smem reads of final slab done; G bufs reusable as t2_s
    #pragma unroll
    for (int mf = 0; mf < 2; ++mf) {
        int e0 = ebq + mf * 16 + lane / 4;
        #pragma unroll
        for (int nf = 0; nf < 6; ++nf) {
            int i0 = (nbase + nf) * 8 + (lane & 3) * 2;
            t2_s[(i0    ) * EB + e0    ] = acc[mf][nf][0];
            t2_s[(i0 + 1) * EB + e0    ] = acc[mf][nf][1];
            t2_s[(i0    ) * EB + e0 + 8] = acc[mf][nf][2];
            t2_s[(i0 + 1) * EB + e0 + 8] = acc[mf][nf][3];
        }
    }
    __syncthreads();

    // --- epilogue: conv = t2 . basis2 ; scores ; v  (o-range split by sub) ---
    {
        float b2r[8];
        #pragma unroll
        for (int z = 0; z < 8; ++z) b2r[z] = b2[e * 8 + z];   // [p][d]

        float sc0 = 0.f, sc1 = 0.f;        // heads sub*2, sub*2+1
        #pragma unroll
        for (int o8 = 0; o8 < 8; ++o8) {
            int o = sub * 8 + o8;
            float a0 = t2_s[(2 * o) * EB + el],      a1 = t2_s[(2 * o + 1) * EB + el];
            float q0 = t2_s[(2 * o + 32) * EB + el], q1 = t2_s[(2 * o + 33) * EB + el];
            float dot = 0.f;
            #pragma unroll
            for (int d = 0; d < 4; ++d) {
                float kk = a0 * b2r[d] + a1 * b2r[4 + d];
                float qq = q0 * b2r[d] + q1 * b2r[4 + d];
                dot = fmaf(kk, qq, dot);
            }
            if (o8 < 4) sc0 += dot; else sc1 += dot;
        }
        #pragma unroll
        for (int o8 = 0; o8 < 8; ++o8) {
            int o = sub * 8 + o8;
            float a0 = t2_s[(2 * o + 64) * EB + el], a1 = t2_s[(2 * o + 65) * EB + el];
            float4 vv;
            vv.x = a0 * b2r[0] + a1 * b2r[4];
            vv.y = a0 * b2r[1] + a1 * b2r[5];
            vv.z = a0 * b2r[2] + a1 * b2r[6];
            vv.w = a0 * b2r[3] + a1 * b2r[7];
            reinterpret_cast<float4*>(g_v)[e * 16 + o] = vv;
        }
        const int dn = dst_idx[e];
        #pragma unroll
        for (int hq = 0; hq < 2; ++hq) {
            int hh = sub * 2 + hq;
            float s = (hq == 0 ? sc0 : sc1) * 0.125f;   // TEMP = HS^-0.5
            s = (s > 0.f) ? s : 0.2f * s;               // leaky_relu(., 0.2)
            g_scores[e * NH + hh] = s;
            atomicMaxF(&g_nmax[dn * NH + hh], s);
        }
    }
}

// ---------------- kernel 2: softmax denominator ----------------
__global__ void k_sum(const int* __restrict__ dst_idx) {
    int idx = blockIdx.x * blockDim.x + threadIdx.x;
    if (idx >= EE * NH) return;
    int e = idx >> 2, hh = idx & 3;
    int dn = dst_idx[e];
    float ex = expf(g_scores[idx] - g_nmax[dn * NH + hh]);
    atomicAdd(&g_nsum[dn * NH + hh], ex);
}

// ---------------- kernel 3: weighted aggregation (copy_e_sum) ----------------
__global__ void k_agg(const int* __restrict__ dst_idx) {
    int idx = blockIdx.x * blockDim.x + threadIdx.x;
    if (idx >= EE * HS) return;
    int e = idx >> 6, x = idx & 63, hh = x >> 4;
    int dn = dst_idx[e];
    float w = expf(g_scores[e * NH + hh] - g_nmax[dn * NH + hh]) / g_nsum[dn * NH + hh];
    atomicAdd(&g_agg[dn * HS + x], w * g_v[idx]);
}

// ---------------- kernel 4: per-irrep equivariant projection ----------------
__global__ void k_proj(const float* __restrict__ pw, const float* __restrict__ pb,
                       float* __restrict__ out) {
    int idx = blockIdx.x * blockDim.x + threadIdx.x;
    if (idx >= NN * HS) return;
    int n  = idx >> 6;
    int m2 = (idx >> 2) & 15;
    int d  = idx & 3;
    int blk = (d == 0) ? 0 : 1;                // IRREP_IDX = [0,1,1,1]
    const float* pwr = pw + (blk * M2 + m2) * M2;
    float s = (d == 0) ? pb[m2] : 0.f;
    #pragma unroll
    for (int m = 0; m < M2; ++m) s = fmaf(pwr[m], g_agg[n * HS + m * 4 + d], s);
    out[idx] = s;
}

// ---------------- launch ----------------
extern "C" void kernel_launch(void* const* d_in, const int* in_sizes, int n_in,
                              void* d_out, int out_size) {
    const float* ef    = (const float*)d_in[0];   // edge_feats (E,32)
    const float* f     = (const float*)d_in[1];   // f (N,16,4)
    const float* b1    = (const float*)d_in[2];   // basis1 (E,4,2)
    const float* b2    = (const float*)d_in[3];   // basis2 (E,2,4)
    const int*   src   = (const int*)  d_in[4];   // src_idx (E)
    const int*   dst   = (const int*)  d_in[5];   // dst_idx (E)
    const float* w1    = (const float*)d_in[6];   // rw_w1 (32,64)
    const float* bias1 = (const float*)d_in[7];   // rw_bias1 (64)
    const float* w2    = (const float*)d_in[8];   // rw_w2 (64,3072)
    const float* bias2 = (const float*)d_in[9];   // rw_bias2 (3072)
    const float* pw    = (const float*)d_in[10];  // proj_w (32,16)
    const float* pb    = (const float*)d_in[11];  // proj_b (16,1)
    float* out = (float*)d_out;

    (void)in_sizes; (void)n_in; (void)out_size;

    cudaFuncSetAttribute(k_edge, cudaFuncAttributeMaxDynamicSharedMemorySize, SMEM_BYTES);

    k_prepB<<<(NSLAB * 4 * 12 * 32 + 255) / 256, 256>>>(w2, bias2);
    k_hid<<<EE / 256, 256>>>(ef, w1, bias1);
    k_init<<<(NN * HS + 255) / 256, 256>>>();
    k_edge<<<EE / EB, NT, SMEM_BYTES>>>(f, b1, b2, src, dst);
    k_sum<<<(EE * NH + 255) / 256, 256>>>(dst);
    k_agg<<<(EE * HS + 255) / 256, 256>>>(dst);
    k_proj<<<(NN * HS + 255) / 256, 256>>>(pw, pb, out);
}